// round 12
// baseline (speedup 1.0000x reference)
#include <cuda_runtime.h>
#include <cstdint>

#define BATCH 32
#define SEQ   1024
#define DHEAD 64
#define SCALE 0.125f
#define OUT_ELEMS (BATCH * SEQ * DHEAD)

// ---- packed fp16x2 globals (written by prep kernel) -------------------------
#define NPAIRS (BATCH * SEQ * 32)          // 1,048,576 uint32 each
__device__ uint32_t g_w16[NPAIRS];         // K + R
__device__ uint32_t g_v16[NPAIRS];         // V

// ---- split-K partial scratch ------------------------------------------------
__device__ float g_pvp[2][OUT_ELEMS];      // partial PV (unnormalized)
__device__ float g_denp[2][BATCH * SEQ];   // partial exp-sums

// ---- smem layout: rows padded to 72 fp16 = 144 B ----------------------------
#define ROWB   144
#define Q_O    0                            // 128 x 144 = 18432
#define STAGE0 18432
#define STG_SZ 18432                        // W 64x144 + V 64x144
#define W_S    0
#define V_S    9216
#define SMEM_TOTAL (STAGE0 + 2 * STG_SZ)    // 55296 B

__device__ __forceinline__ uint32_t s2u(const void* p) {
    uint32_t a;
    asm("{ .reg .u64 t; cvta.to.shared.u64 t, %1; cvt.u32.u64 %0, t; }" : "=r"(a) : "l"(p));
    return a;
}
__device__ __forceinline__ uint32_t pack_f16x2(float lo, float hi) {
    uint32_t r;
    asm("cvt.rn.f16x2.f32 %0, %1, %2;" : "=r"(r) : "f"(hi), "f"(lo));
    return r;
}

#define LDSM_X4(r0, r1, r2, r3, a) \
    asm volatile("ldmatrix.sync.aligned.m8n8.x4.shared.b16 {%0,%1,%2,%3}, [%4];" \
        : "=r"(r0), "=r"(r1), "=r"(r2), "=r"(r3) : "r"(a))
#define LDSM_X4T(r0, r1, r2, r3, a) \
    asm volatile("ldmatrix.sync.aligned.m8n8.x4.trans.shared.b16 {%0,%1,%2,%3}, [%4];" \
        : "=r"(r0), "=r"(r1), "=r"(r2), "=r"(r3) : "r"(a))
#define MMA16816(c, a0, a1, a2, a3, b0, b1) \
    asm volatile("mma.sync.aligned.m16n8k16.row.col.f32.f16.f16.f32 " \
        "{%0,%1,%2,%3}, {%4,%5,%6,%7}, {%8,%9}, {%0,%1,%2,%3};" \
        : "+f"((c)[0]), "+f"((c)[1]), "+f"((c)[2]), "+f"((c)[3]) \
        : "r"(a0), "r"(a1), "r"(a2), "r"(a3), "r"(b0), "r"(b1))

#define CP16(dst, src) \
    asm volatile("cp.async.cg.shared.global [%0], [%1], 16;" :: "r"(dst), "l"(src))
#define CPCOMMIT() asm volatile("cp.async.commit_group;" ::: "memory")
#define CPWAIT1()  asm volatile("cp.async.wait_group 1;" ::: "memory")

// =============================================================================
// Prep: pack W=K+R and V into fp16x2. 2 pairs (float4) per thread for MLP.
// =============================================================================
__global__ void __launch_bounds__(256) prep_kernel(const float* __restrict__ K,
                                                   const float* __restrict__ V,
                                                   const float* __restrict__ R) {
    int i = blockIdx.x * 256 + threadIdx.x;       // float4 index
    size_t e = (size_t)i * 4;
    float4 k = *reinterpret_cast<const float4*>(K + e);
    float4 r = *reinterpret_cast<const float4*>(R + e);
    float4 v = *reinterpret_cast<const float4*>(V + e);
    uint2 wo, vo;
    wo.x = pack_f16x2(k.x + r.x, k.y + r.y);
    wo.y = pack_f16x2(k.z + r.z, k.w + r.w);
    vo.x = pack_f16x2(v.x, v.y);
    vo.y = pack_f16x2(v.z, v.w);
    reinterpret_cast<uint2*>(g_w16)[i] = wo;
    reinterpret_cast<uint2*>(g_v16)[i] = vo;
}

// ---- cp.async staging: W + V tile (64 keys x 32 pairs each), 128 threads -----
__device__ __forceinline__ void stage_tile(uint32_t sb, uint32_t stagebase,
                                           int b, int key0, int tid) {
    #pragma unroll
    for (int l = 0; l < 8; l++) {
        int idx = tid + l * 128;                 // 0..1023
        const int arr = l >> 2;                  // 0: W, 1: V
        int rem = idx & 511;
        int row = rem >> 3, c = rem & 7;
        const uint32_t* gs = arr ? g_v16 : g_w16;
        uint32_t dst = sb + stagebase + (uint32_t)arr * 9216u
                     + (uint32_t)row * ROWB + (uint32_t)c * 16u;
        const char* src = (const char*)gs
                        + (((size_t)(b * SEQ + key0 + row)) * 32 + (size_t)c * 4) * 4;
        CP16(dst, src);
    }
}

// =============================================================================
// Fused attention, split-K + split-acc: CTA = 128 Q-rows x 512 keys.
// 4 warps x 32 rows; 64-key tiles processed as two 32-key passes (~168 regs).
// grid = (2 key-halves, 8 row-tiles, 32 batch) = 512 CTAs, 3 CTAs/SM.
// =============================================================================
__global__ void __launch_bounds__(128, 3)
attn_kernel(const float* __restrict__ Q, float* __restrict__ S) {
    extern __shared__ char smem[];
    const uint32_t sb = s2u(smem);

    const int tid  = threadIdx.x;
    const int lane = tid & 31;
    const int w    = tid >> 5;       // 0..3
    const int kh   = blockIdx.x;     // key half: 0 or 1
    const int n0   = blockIdx.y * 128;
    const int b    = blockIdx.z;
    const int g    = lane >> 2;
    const int tg   = lane & 3;
    const int it0  = kh * 8;

    // ---- prologue: kick off W/V stages, pack Q inline ------------------------
    stage_tile(sb, STAGE0, b, it0 * 64, tid);
    CPCOMMIT();
    stage_tile(sb, STAGE0 + STG_SZ, b, (it0 + 1) * 64, tid);
    CPCOMMIT();

    #pragma unroll
    for (int l = 0; l < 8; l++) {
        int idx = tid + l * 128;                 // 0..1023
        int row = idx >> 3, c = idx & 7;         // c: group of 4 pairs
        const float2* qs = reinterpret_cast<const float2*>(
            Q + ((size_t)(b * SEQ + n0 + row)) * DHEAD + c * 8);
        uint32_t* dst = reinterpret_cast<uint32_t*>(
            smem + Q_O + (uint32_t)row * ROWB + (uint32_t)c * 16u);
        #pragma unroll
        for (int p = 0; p < 4; p++) {
            float2 q = qs[p];
            dst[p] = pack_f16x2(q.x * SCALE, q.y * SCALE);
        }
    }
    CPWAIT1();
    __syncthreads();

    // ---- hoist Q fragments: 2 row-tiles x 4 k-steps ---------------------------
    uint32_t qf[2][4][4];
    #pragma unroll
    for (int mt = 0; mt < 2; mt++)
        #pragma unroll
        for (int ks = 0; ks < 4; ks++) {
            uint32_t qa = sb + Q_O
                        + (uint32_t)(w * 32 + mt * 16 + (lane & 15)) * ROWB
                        + (uint32_t)(ks * 16 + (lane >> 4) * 8) * 2;
            LDSM_X4(qf[mt][ks][0], qf[mt][ks][1], qf[mt][ks][2], qf[mt][ks][3], qa);
        }

    float pv[2][8][4];
    #pragma unroll
    for (int mt = 0; mt < 2; mt++)
        #pragma unroll
        for (int j = 0; j < 8; j++)
            #pragma unroll
            for (int p = 0; p < 4; p++) pv[mt][j][p] = 0.0f;
    float den[2][2] = {{0.0f, 0.0f}, {0.0f, 0.0f}};

    float* SrowA = S + ((size_t)(b * SEQ + n0 + w * 32 + g)) * SEQ;          // mt=0
    float* SrowB = SrowA + (size_t)16 * SEQ;                                  // mt=1

    for (int it = 0; it < 8; it++) {
        const uint32_t stb = sb + STAGE0 + (uint32_t)(it & 1) * STG_SZ;
        const int key0 = (it0 + it) * 64;

        #pragma unroll
        for (int pass = 0; pass < 2; pass++) {
            const int kb = pass * 32;

            // ---- MMA1: 32-key half, acc[2 row-tiles][4 col-grps][4] ----------
            float acc[2][4][4];
            #pragma unroll
            for (int mt = 0; mt < 2; mt++)
                #pragma unroll
                for (int j = 0; j < 4; j++)
                    #pragma unroll
                    for (int p = 0; p < 4; p++) acc[mt][j][p] = 0.0f;

            #pragma unroll
            for (int ks = 0; ks < 4; ks++) {
                #pragma unroll
                for (int nt = 0; nt < 2; nt++) {
                    uint32_t wa = stb + W_S
                                + (uint32_t)(kb + nt * 16 + (lane & 7) + ((lane >> 4) & 1) * 8) * ROWB
                                + (uint32_t)(ks * 16 + ((lane >> 3) & 1) * 8) * 2;
                    uint32_t b0, b1, b2, b3;
                    LDSM_X4(b0, b1, b2, b3, wa);
                    #pragma unroll
                    for (int mt = 0; mt < 2; mt++) {
                        MMA16816(acc[mt][nt * 2],     qf[mt][ks][0], qf[mt][ks][1],
                                 qf[mt][ks][2], qf[mt][ks][3], b0, b1);
                        MMA16816(acc[mt][nt * 2 + 1], qf[mt][ks][0], qf[mt][ks][1],
                                 qf[mt][ks][2], qf[mt][ks][3], b2, b3);
                    }
                }
            }

            // ---- epilogue (S out, exp, denom, P frags) + MMA2 -----------------
            #pragma unroll
            for (int kk = 0; kk < 2; kk++) {
                uint32_t a[2][4];
                #pragma unroll
                for (int mt = 0; mt < 2; mt++) {
                    float* c0 = acc[mt][kk * 2];
                    float* c1 = acc[mt][kk * 2 + 1];
                    int col = key0 + kb + kk * 16 + tg * 2;
                    float* Sr0 = (mt ? SrowB : SrowA);
                    float* Sr1 = Sr0 + (size_t)8 * SEQ;
                    *reinterpret_cast<float2*>(Sr0 + col)     = make_float2(c0[0], c0[1]);
                    *reinterpret_cast<float2*>(Sr1 + col)     = make_float2(c0[2], c0[3]);
                    *reinterpret_cast<float2*>(Sr0 + col + 8) = make_float2(c1[0], c1[1]);
                    *reinterpret_cast<float2*>(Sr1 + col + 8) = make_float2(c1[2], c1[3]);

                    float p00 = __expf(c0[0]), p01 = __expf(c0[1]);
                    float p02 = __expf(c0[2]), p03 = __expf(c0[3]);
                    float p10 = __expf(c1[0]), p11 = __expf(c1[1]);
                    float p12 = __expf(c1[2]), p13 = __expf(c1[3]);
                    den[mt][0] += p00 + p01 + p10 + p11;
                    den[mt][1] += p02 + p03 + p12 + p13;

                    a[mt][0] = pack_f16x2(p00, p01);
                    a[mt][1] = pack_f16x2(p02, p03);
                    a[mt][2] = pack_f16x2(p10, p11);
                    a[mt][3] = pack_f16x2(p12, p13);
                }
                #pragma unroll
                for (int dj2 = 0; dj2 < 4; dj2++) {
                    uint32_t va = stb + V_S
                                + (uint32_t)(kb + kk * 16 + (lane & 7) + ((lane >> 3) & 1) * 8) * ROWB
                                + (uint32_t)(dj2 * 16 + ((lane >> 4) & 1) * 8) * 2;
                    uint32_t v0, v1, v2, v3;
                    LDSM_X4T(v0, v1, v2, v3, va);
                    #pragma unroll
                    for (int mt = 0; mt < 2; mt++) {
                        MMA16816(pv[mt][dj2 * 2],     a[mt][0], a[mt][1], a[mt][2], a[mt][3], v0, v1);
                        MMA16816(pv[mt][dj2 * 2 + 1], a[mt][0], a[mt][1], a[mt][2], a[mt][3], v2, v3);
                    }
                }
            }
        }

        __syncthreads();                        // done reading this buffer
        if (it + 2 < 8)
            stage_tile(sb, STAGE0 + (uint32_t)(it & 1) * STG_SZ, b, (it0 + it + 2) * 64, tid);
        CPCOMMIT();
        CPWAIT1();                               // next tile ready
        __syncthreads();
    }

    // ---- finalize: quad-reduce denominators, write partials -------------------
    #pragma unroll
    for (int mt = 0; mt < 2; mt++) {
        #pragma unroll
        for (int h2 = 0; h2 < 2; h2++) {
            den[mt][h2] += __shfl_xor_sync(0xffffffffu, den[mt][h2], 1);
            den[mt][h2] += __shfl_xor_sync(0xffffffffu, den[mt][h2], 2);
        }
        int grow0 = b * SEQ + n0 + w * 32 + mt * 16 + g;
        if (tg == 0) {
            g_denp[kh][grow0]     = den[mt][0];
            g_denp[kh][grow0 + 8] = den[mt][1];
        }
        float* P0 = g_pvp[kh] + (size_t)grow0 * DHEAD;
        float* P1 = P0 + (size_t)8 * DHEAD;
        #pragma unroll
        for (int dj = 0; dj < 8; dj++) {
            int col = dj * 8 + tg * 2;
            *reinterpret_cast<float2*>(P0 + col) = make_float2(pv[mt][dj][0], pv[mt][dj][1]);
            *reinterpret_cast<float2*>(P1 + col) = make_float2(pv[mt][dj][2], pv[mt][dj][3]);
        }
    }
}

// =============================================================================
// Combine: out = (pv0 + pv1) / (den0 + den1), float4 granularity.
// =============================================================================
__global__ void __launch_bounds__(256) combine_kernel(float* __restrict__ Out) {
    int i = blockIdx.x * 256 + threadIdx.x;       // float4 index, 0..524287
    int row = i >> 4;                             // 16 float4s per 64-float row
    float4 a = reinterpret_cast<const float4*>(g_pvp[0])[i];
    float4 c = reinterpret_cast<const float4*>(g_pvp[1])[i];
    float rinv = 1.0f / (g_denp[0][row] + g_denp[1][row]);
    reinterpret_cast<float4*>(Out)[i] =
        make_float4((a.x + c.x) * rinv, (a.y + c.y) * rinv,
                    (a.z + c.z) * rinv, (a.w + c.w) * rinv);
}

// =============================================================================
extern "C" void kernel_launch(void* const* d_in, const int* in_sizes, int n_in,
                              void* d_out, int out_size) {
    const float* Q = (const float*)d_in[0];
    const float* K = (const float*)d_in[1];
    const float* V = (const float*)d_in[2];
    const float* R = (const float*)d_in[3];

    float* out = (float*)d_out;
    float* S   = out + OUT_ELEMS;

    prep_kernel<<<(NPAIRS / 2) / 256, 256>>>(K, V, R);

    cudaFuncSetAttribute(attn_kernel, cudaFuncAttributeMaxDynamicSharedMemorySize,
                         SMEM_TOTAL);
    attn_kernel<<<dim3(2, SEQ / 128, BATCH), 128, SMEM_TOTAL>>>(Q, S);

    combine_kernel<<<(OUT_ELEMS / 4) / 256, 256>>>(out);
}

// round 15
// speedup vs baseline: 1.1892x; 1.1892x over previous
#include <cuda_runtime.h>
#include <cstdint>

#define BATCH 32
#define SEQ   1024
#define DHEAD 64
#define SCALE 0.125f
#define OUT_ELEMS (BATCH * SEQ * DHEAD)

// ---- packed fp16x2 globals (written by prep kernel) -------------------------
#define NPAIRS (BATCH * SEQ * 32)          // 1,048,576 uint32 each
__device__ uint32_t g_w16[NPAIRS];         // K + R
__device__ uint32_t g_v16[NPAIRS];         // V

// ---- smem layout: rows padded to 72 fp16 = 144 B ----------------------------
#define ROWB   144
#define Q_O    0                            // 128 x 144 = 18432
#define STAGE0 18432
#define STG_SZ 18432                        // W 64x144 + V 64x144
#define W_S    0
#define V_S    9216
#define SMEM_TOTAL (STAGE0 + 2 * STG_SZ)    // 55296 B

__device__ __forceinline__ uint32_t s2u(const void* p) {
    uint32_t a;
    asm("{ .reg .u64 t; cvta.to.shared.u64 t, %1; cvt.u32.u64 %0, t; }" : "=r"(a) : "l"(p));
    return a;
}
__device__ __forceinline__ uint32_t pack_f16x2(float lo, float hi) {
    uint32_t r;
    asm("cvt.rn.f16x2.f32 %0, %1, %2;" : "=r"(r) : "f"(hi), "f"(lo));
    return r;
}

#define LDSM_X4(r0, r1, r2, r3, a) \
    asm volatile("ldmatrix.sync.aligned.m8n8.x4.shared.b16 {%0,%1,%2,%3}, [%4];" \
        : "=r"(r0), "=r"(r1), "=r"(r2), "=r"(r3) : "r"(a))
#define LDSM_X4T(r0, r1, r2, r3, a) \
    asm volatile("ldmatrix.sync.aligned.m8n8.x4.trans.shared.b16 {%0,%1,%2,%3}, [%4];" \
        : "=r"(r0), "=r"(r1), "=r"(r2), "=r"(r3) : "r"(a))
#define MMA16816(c, a0, a1, a2, a3, b0, b1) \
    asm volatile("mma.sync.aligned.m16n8k16.row.col.f32.f16.f16.f32 " \
        "{%0,%1,%2,%3}, {%4,%5,%6,%7}, {%8,%9}, {%0,%1,%2,%3};" \
        : "+f"((c)[0]), "+f"((c)[1]), "+f"((c)[2]), "+f"((c)[3]) \
        : "r"(a0), "r"(a1), "r"(a2), "r"(a3), "r"(b0), "r"(b1))

#define CP16(dst, src) \
    asm volatile("cp.async.cg.shared.global [%0], [%1], 16;" :: "r"(dst), "l"(src))
#define CPCOMMIT() asm volatile("cp.async.commit_group;" ::: "memory")
#define CPWAIT1()  asm volatile("cp.async.wait_group 1;" ::: "memory")

// =============================================================================
// Prep: pack W=K+R and V into fp16x2. 2 pairs (float4) per thread.
// =============================================================================
__global__ void __launch_bounds__(256) prep_kernel(const float* __restrict__ K,
                                                   const float* __restrict__ V,
                                                   const float* __restrict__ R) {
    int i = blockIdx.x * 256 + threadIdx.x;       // float4 index
    size_t e = (size_t)i * 4;
    float4 k = *reinterpret_cast<const float4*>(K + e);
    float4 r = *reinterpret_cast<const float4*>(R + e);
    float4 v = *reinterpret_cast<const float4*>(V + e);
    uint2 wo, vo;
    wo.x = pack_f16x2(k.x + r.x, k.y + r.y);
    wo.y = pack_f16x2(k.z + r.z, k.w + r.w);
    vo.x = pack_f16x2(v.x, v.y);
    vo.y = pack_f16x2(v.z, v.w);
    reinterpret_cast<uint2*>(g_w16)[i] = wo;
    reinterpret_cast<uint2*>(g_v16)[i] = vo;
}

// ---- cp.async staging: W + V tile (64 keys x 32 pairs each), 128 threads -----
__device__ __forceinline__ void stage_tile(uint32_t sb, uint32_t stagebase,
                                           int b, int key0, int tid) {
    #pragma unroll
    for (int l = 0; l < 8; l++) {
        int idx = tid + l * 128;                 // 0..1023
        const int arr = l >> 2;                  // 0: W, 1: V
        int rem = idx & 511;
        int row = rem >> 3, c = rem & 7;
        const uint32_t* gs = arr ? g_v16 : g_w16;
        uint32_t dst = sb + stagebase + (uint32_t)arr * 9216u
                     + (uint32_t)row * ROWB + (uint32_t)c * 16u;
        const char* src = (const char*)gs
                        + (((size_t)(b * SEQ + key0 + row)) * 32 + (size_t)c * 4) * 4;
        CP16(dst, src);
    }
}

// =============================================================================
// Fused attention: CTA = 128 Q-rows, 4 warps x 32 rows (2 row-tiles of 16).
// 64-key tiles, full accumulator (round-8 engine). 128 threads, 2 CTAs/SM.
// =============================================================================
__global__ void __launch_bounds__(128, 2)
attn_kernel(const float* __restrict__ Q, float* __restrict__ S,
            float* __restrict__ Out) {
    extern __shared__ char smem[];
    const uint32_t sb = s2u(smem);

    const int tid  = threadIdx.x;
    const int lane = tid & 31;
    const int w    = tid >> 5;       // 0..3
    const int b    = blockIdx.y;
    const int n0   = blockIdx.x * 128;
    const int g    = lane >> 2;
    const int tg   = lane & 3;

    // ---- prologue: kick off W/V stages, pack Q inline ------------------------
    stage_tile(sb, STAGE0, b, 0, tid);
    CPCOMMIT();
    stage_tile(sb, STAGE0 + STG_SZ, b, 64, tid);
    CPCOMMIT();

    #pragma unroll
    for (int l = 0; l < 8; l++) {
        int idx = tid + l * 128;                 // 0..1023
        int row = idx >> 3, c = idx & 7;         // c: group of 4 pairs
        const float2* qs = reinterpret_cast<const float2*>(
            Q + ((size_t)(b * SEQ + n0 + row)) * DHEAD + c * 8);
        uint32_t* dst = reinterpret_cast<uint32_t*>(
            smem + Q_O + (uint32_t)row * ROWB + (uint32_t)c * 16u);
        #pragma unroll
        for (int p = 0; p < 4; p++) {
            float2 q = qs[p];
            dst[p] = pack_f16x2(q.x * SCALE, q.y * SCALE);
        }
    }
    CPWAIT1();
    __syncthreads();

    // ---- hoist Q fragments: 2 row-tiles x 4 k-steps ---------------------------
    uint32_t qf[2][4][4];
    #pragma unroll
    for (int mt = 0; mt < 2; mt++)
        #pragma unroll
        for (int ks = 0; ks < 4; ks++) {
            uint32_t qa = sb + Q_O
                        + (uint32_t)(w * 32 + mt * 16 + (lane & 15)) * ROWB
                        + (uint32_t)(ks * 16 + (lane >> 4) * 8) * 2;
            LDSM_X4(qf[mt][ks][0], qf[mt][ks][1], qf[mt][ks][2], qf[mt][ks][3], qa);
        }

    float pv[2][8][4];
    #pragma unroll
    for (int mt = 0; mt < 2; mt++)
        #pragma unroll
        for (int j = 0; j < 8; j++)
            #pragma unroll
            for (int p = 0; p < 4; p++) pv[mt][j][p] = 0.0f;
    float den[2][2] = {{0.0f, 0.0f}, {0.0f, 0.0f}};

    float* SrowA = S + ((size_t)(b * SEQ + n0 + w * 32 + g)) * SEQ;          // mt=0
    float* SrowB = SrowA + (size_t)16 * SEQ;                                  // mt=1

    for (int it = 0; it < 16; it++) {
        const uint32_t stb = sb + STAGE0 + (uint32_t)(it & 1) * STG_SZ;
        const int key0 = it * 64;

        // ---- MMA1: S-tile = Q (K+R)^T, acc[2 row-tiles][8 col-grps][4] -------
        float acc[2][8][4];
        #pragma unroll
        for (int mt = 0; mt < 2; mt++)
            #pragma unroll
            for (int j = 0; j < 8; j++)
                #pragma unroll
                for (int p = 0; p < 4; p++) acc[mt][j][p] = 0.0f;

        #pragma unroll
        for (int ks = 0; ks < 4; ks++) {
            #pragma unroll
            for (int nt = 0; nt < 4; nt++) {
                uint32_t wa = stb + W_S
                            + (uint32_t)(nt * 16 + (lane & 7) + ((lane >> 4) & 1) * 8) * ROWB
                            + (uint32_t)(ks * 16 + ((lane >> 3) & 1) * 8) * 2;
                uint32_t b0, b1, b2, b3;
                LDSM_X4(b0, b1, b2, b3, wa);
                #pragma unroll
                for (int mt = 0; mt < 2; mt++) {
                    MMA16816(acc[mt][nt * 2],     qf[mt][ks][0], qf[mt][ks][1],
                             qf[mt][ks][2], qf[mt][ks][3], b0, b1);
                    MMA16816(acc[mt][nt * 2 + 1], qf[mt][ks][0], qf[mt][ks][1],
                             qf[mt][ks][2], qf[mt][ks][3], b2, b3);
                }
            }
        }

        // ---- epilogue (S out, exp, denom, P frags) + MMA2 ---------------------
        #pragma unroll
        for (int kk = 0; kk < 4; kk++) {
            uint32_t a[2][4];
            #pragma unroll
            for (int mt = 0; mt < 2; mt++) {
                float* c0 = acc[mt][kk * 2];
                float* c1 = acc[mt][kk * 2 + 1];
                int col = key0 + kk * 16 + tg * 2;
                float* Sr0 = (mt ? SrowB : SrowA);
                float* Sr1 = Sr0 + (size_t)8 * SEQ;
                *reinterpret_cast<float2*>(Sr0 + col)     = make_float2(c0[0], c0[1]);
                *reinterpret_cast<float2*>(Sr1 + col)     = make_float2(c0[2], c0[3]);
                *reinterpret_cast<float2*>(Sr0 + col + 8) = make_float2(c1[0], c1[1]);
                *reinterpret_cast<float2*>(Sr1 + col + 8) = make_float2(c1[2], c1[3]);

                float p00 = __expf(c0[0]), p01 = __expf(c0[1]);
                float p02 = __expf(c0[2]), p03 = __expf(c0[3]);
                float p10 = __expf(c1[0]), p11 = __expf(c1[1]);
                float p12 = __expf(c1[2]), p13 = __expf(c1[3]);
                den[mt][0] += p00 + p01 + p10 + p11;
                den[mt][1] += p02 + p03 + p12 + p13;

                a[mt][0] = pack_f16x2(p00, p01);
                a[mt][1] = pack_f16x2(p02, p03);
                a[mt][2] = pack_f16x2(p10, p11);
                a[mt][3] = pack_f16x2(p12, p13);
            }
            #pragma unroll
            for (int dj2 = 0; dj2 < 4; dj2++) {
                uint32_t va = stb + V_S
                            + (uint32_t)(kk * 16 + (lane & 7) + ((lane >> 3) & 1) * 8) * ROWB
                            + (uint32_t)(dj2 * 16 + ((lane >> 4) & 1) * 8) * 2;
                uint32_t v0, v1, v2, v3;
                LDSM_X4T(v0, v1, v2, v3, va);
                #pragma unroll
                for (int mt = 0; mt < 2; mt++) {
                    MMA16816(pv[mt][dj2 * 2],     a[mt][0], a[mt][1], a[mt][2], a[mt][3], v0, v1);
                    MMA16816(pv[mt][dj2 * 2 + 1], a[mt][0], a[mt][1], a[mt][2], a[mt][3], v2, v3);
                }
            }
        }

        __syncthreads();                        // done reading this buffer
        if (it + 2 < 16)
            stage_tile(sb, STAGE0 + (uint32_t)(it & 1) * STG_SZ, b, (it + 2) * 64, tid);
        CPCOMMIT();
        CPWAIT1();                               // next tile ready
        __syncthreads();
    }

    // ---- finalize: quad-reduce denominators, write out ------------------------
    #pragma unroll
    for (int mt = 0; mt < 2; mt++) {
        #pragma unroll
        for (int h2 = 0; h2 < 2; h2++) {
            den[mt][h2] += __shfl_xor_sync(0xffffffffu, den[mt][h2], 1);
            den[mt][h2] += __shfl_xor_sync(0xffffffffu, den[mt][h2], 2);
        }
        float ri0 = 1.0f / den[mt][0];
        float ri1 = 1.0f / den[mt][1];
        float* O0 = Out + ((size_t)(b * SEQ + n0 + w * 32 + mt * 16 + g)) * DHEAD;
        float* O1 = O0 + (size_t)8 * DHEAD;
        #pragma unroll
        for (int dj = 0; dj < 8; dj++) {
            int col = dj * 8 + tg * 2;
            *reinterpret_cast<float2*>(O0 + col) =
                make_float2(pv[mt][dj][0] * ri0, pv[mt][dj][1] * ri0);
            *reinterpret_cast<float2*>(O1 + col) =
                make_float2(pv[mt][dj][2] * ri1, pv[mt][dj][3] * ri1);
        }
    }
}

// =============================================================================
extern "C" void kernel_launch(void* const* d_in, const int* in_sizes, int n_in,
                              void* d_out, int out_size) {
    const float* Q = (const float*)d_in[0];
    const float* K = (const float*)d_in[1];
    const float* V = (const float*)d_in[2];
    const float* R = (const float*)d_in[3];

    float* out = (float*)d_out;
    float* S   = out + OUT_ELEMS;

    prep_kernel<<<(NPAIRS / 2) / 256, 256>>>(K, V, R);

    cudaFuncSetAttribute(attn_kernel, cudaFuncAttributeMaxDynamicSharedMemorySize,
                         SMEM_TOTAL);
    attn_kernel<<<dim3(SEQ / 128, BATCH), 128, SMEM_TOTAL>>>(Q, S, out);
}